// round 1
// baseline (speedup 1.0000x reference)
#include <cuda_runtime.h>
#include <cuda_bf16.h>
#include <math.h>

// Problem constants
#define BATCH 8
#define CIN   64
#define HEADS 2
#define CH    32          // channels per head
#define IMG   256
#define HW    65536       // IMG*IMG

// ---------------- scratch (static device globals; no allocation allowed) ----
__device__ float g_y1[(size_t)BATCH * 192 * HW];   // qkv after 1x1 conv (402 MB)
__device__ float g_v [(size_t)BATCH * 64  * HW];   // v after dwconv     (134 MB)
__device__ float g_gram[BATCH * HEADS * CH * CH];  // q.k^T Gram per (b,head)
__device__ float g_sqq [BATCH * HEADS * CH];       // sum q^2 per channel
__device__ float g_sqk [BATCH * HEADS * CH];       // sum k^2 per channel
__device__ float g_weff[BATCH * 64 * 64];          // folded proj*attn matrix

// ---------------- K0: zero accumulators (graph replays re-run this) ---------
__global__ void k0_zero() {
    int i = blockIdx.x * 256 + threadIdx.x;
    if (i < BATCH * HEADS * CH * CH) g_gram[i] = 0.f;
    if (i < BATCH * HEADS * CH) { g_sqq[i] = 0.f; g_sqk[i] = 0.f; }
}

// ---------------- K1: 1x1 conv  y1[b,o,n] = sum_c wqkv[o,c]*x[b,c,n] --------
// grid (3 groups of 64 out-ch, 256 pixel-blocks, 8 batches), 256 threads.
// Thread: 16 out-channels x 4 pixels register tile.
__global__ void __launch_bounds__(256) k1_conv1x1(const float* __restrict__ x,
                                                  const float* __restrict__ wqkv) {
    int g  = blockIdx.x;             // 0..2
    int pb = blockIdx.y;             // 0..255
    int b  = blockIdx.z;
    __shared__ float ws[64 * 64];    // [o_local][c]
    int tid = threadIdx.x;
    for (int i = tid; i < 4096; i += 256) ws[i] = wqkv[g * 4096 + i];
    __syncthreads();

    int ot = tid >> 6;               // 0..3 -> outs [ot*16, ot*16+16)
    int qd = tid & 63;               // 0..63 -> 4 pixels
    size_t p0 = (size_t)pb * 256 + qd * 4;
    const float* xb = x + (size_t)b * CIN * HW;

    float acc[16][4];
#pragma unroll
    for (int k = 0; k < 16; k++)
#pragma unroll
        for (int j = 0; j < 4; j++) acc[k][j] = 0.f;

    for (int c = 0; c < 64; c++) {
        float4 xv = *(const float4*)(xb + (size_t)c * HW + p0);
        const float* wr = &ws[(ot * 16) * 64 + c];
#pragma unroll
        for (int k = 0; k < 16; k++) {
            float w = wr[k * 64];
            acc[k][0] += w * xv.x; acc[k][1] += w * xv.y;
            acc[k][2] += w * xv.z; acc[k][3] += w * xv.w;
        }
    }
    float* yb = g_y1 + ((size_t)b * 192 + g * 64) * HW;
#pragma unroll
    for (int k = 0; k < 16; k++) {
        float4 o = make_float4(acc[k][0], acc[k][1], acc[k][2], acc[k][3]);
        *(float4*)(yb + (size_t)(ot * 16 + k) * HW + p0) = o;
    }
}

// ---------------- K2: depthwise 3x3 + Gram/sumsq (heads) or v write ---------
// grid (256 tiles of 16x16 px, 4 groups, 8 batches), 256 threads.
// groups 0,1: head hg -> q ch hg*32+c, k ch 64+hg*32+c -> Gram + sumsq
// groups 2,3: v channel groups -> write g_v
#define QK_PITCH 257
__global__ void __launch_bounds__(256) k2_dw(const float* __restrict__ wdw) {
    int t   = blockIdx.x;
    int grp = blockIdx.y;
    int b   = blockIdx.z;
    int py0 = (t >> 4) * 16, px0 = (t & 15) * 16;
    int tid = threadIdx.x;
    int ly = tid >> 4, lx = tid & 15;

    extern __shared__ float sm[];
    float* halo = sm;                      // 324 floats (18x18)
    float* qt   = sm + 336;                // [32][QK_PITCH]
    float* kt   = qt + 32 * QK_PITCH;      // [32][QK_PITCH]

    bool isHead = (grp < 2);
    int nch = isHead ? 64 : 32;

    for (int c = 0; c < nch; c++) {
        int ych;
        if (isHead) ych = (c < 32) ? (grp * 32 + c) : (64 + grp * 32 + (c - 32));
        else        ych = 128 + (grp - 2) * 32 + c;

        const float* yb = g_y1 + ((size_t)b * 192 + ych) * HW;
        __syncthreads();   // protect halo reuse across channels
        for (int i = tid; i < 324; i += 256) {
            int hy = i / 18, hx = i - hy * 18;
            int gy = py0 - 1 + hy, gx = px0 - 1 + hx;
            float v = 0.f;
            if (gy >= 0 && gy < IMG && gx >= 0 && gx < IMG)
                v = yb[gy * IMG + gx];
            halo[i] = v;
        }
        __syncthreads();

        const float* wd = wdw + ych * 9;
        float w0 = __ldg(wd + 0), w1 = __ldg(wd + 1), w2 = __ldg(wd + 2);
        float w3 = __ldg(wd + 3), w4 = __ldg(wd + 4), w5 = __ldg(wd + 5);
        float w6 = __ldg(wd + 6), w7 = __ldg(wd + 7), w8 = __ldg(wd + 8);

        const float* h0 = &halo[(ly + 0) * 18 + lx];
        const float* h1 = &halo[(ly + 1) * 18 + lx];
        const float* h2 = &halo[(ly + 2) * 18 + lx];
        float acc = h0[0] * w0 + h0[1] * w1 + h0[2] * w2
                  + h1[0] * w3 + h1[1] * w4 + h1[2] * w5
                  + h2[0] * w6 + h2[1] * w7 + h2[2] * w8;

        if (isHead) {
            float* dst = (c < 32) ? &qt[c * QK_PITCH] : &kt[(c - 32) * QK_PITCH];
            dst[ly * 16 + lx] = acc;
        } else {
            int p = (py0 + ly) * IMG + (px0 + lx);
            g_v[((size_t)b * 64 + (grp - 2) * 32 + c) * HW + p] = acc;
        }
    }

    if (!isHead) return;
    __syncthreads();

    // Gram: each thread owns a 2x2 (c,d) tile over 256 pixels.
    int c0 = (tid >> 4) * 2, d0 = (tid & 15) * 2;
    float a00 = 0.f, a01 = 0.f, a10 = 0.f, a11 = 0.f;
#pragma unroll 4
    for (int p = 0; p < 256; p++) {
        float q0 = qt[c0 * QK_PITCH + p], q1 = qt[(c0 + 1) * QK_PITCH + p];
        float k0 = kt[d0 * QK_PITCH + p], k1 = kt[(d0 + 1) * QK_PITCH + p];
        a00 += q0 * k0; a01 += q0 * k1; a10 += q1 * k0; a11 += q1 * k1;
    }
    float* gp = g_gram + ((b * HEADS + grp) * CH) * CH;
    atomicAdd(&gp[(c0 + 0) * CH + d0 + 0], a00);
    atomicAdd(&gp[(c0 + 0) * CH + d0 + 1], a01);
    atomicAdd(&gp[(c0 + 1) * CH + d0 + 0], a10);
    atomicAdd(&gp[(c0 + 1) * CH + d0 + 1], a11);

    if (tid < 32) {
        float s = 0.f;
        for (int p = 0; p < 256; p++) { float q = qt[tid * QK_PITCH + p]; s += q * q; }
        atomicAdd(&g_sqq[(b * HEADS + grp) * CH + tid], s);
    } else if (tid < 64) {
        int c = tid - 32;
        float s = 0.f;
        for (int p = 0; p < 256; p++) { float k = kt[c * QK_PITCH + p]; s += k * k; }
        atomicAdd(&g_sqk[(b * HEADS + grp) * CH + c], s);
    }
}

// ---------------- K3: normalize Gram, triple top-k softmax, fold proj -------
// one block per batch.
__global__ void __launch_bounds__(256) k3_attn(const float* __restrict__ wproj,
                                               const float* __restrict__ temp,
                                               const float* __restrict__ a1p,
                                               const float* __restrict__ a2p,
                                               const float* __restrict__ a3p) {
    int b = blockIdx.x;
    int tid = threadIdx.x;
    __shared__ float attn[HEADS * CH * CH];
    __shared__ float M[HEADS * CH * CH];
    __shared__ float nq[HEADS * CH], nk[HEADS * CH];

    if (tid < 64) {
        nq[tid] = fmaxf(sqrtf(g_sqq[b * 64 + tid]), 1e-12f);
        nk[tid] = fmaxf(sqrtf(g_sqk[b * 64 + tid]), 1e-12f);
    }
    __syncthreads();
    for (int i = tid; i < 2048; i += 256) {
        int head = i >> 10, c = (i >> 5) & 31, d = i & 31;
        attn[i] = g_gram[b * 2048 + i] / (nq[head * 32 + c] * nk[head * 32 + d])
                * temp[head];
    }
    __syncthreads();

    float A1 = a1p[0], A2 = a2p[0], A3 = a3p[0];
    if (tid < 64) {                          // one row (head,c) per thread
        float v[32];
        const float* row = &attn[tid * 32];
#pragma unroll
        for (int i = 0; i < 32; i++) v[i] = row[i];
        float m = v[0];
#pragma unroll
        for (int i = 1; i < 32; i++) m = fmaxf(m, v[i]);

        int rank[32];
        for (int i = 0; i < 32; i++) {
            int r = 0;
            for (int j = 0; j < 32; j++)
                r += (v[j] > v[i]) || (v[j] == v[i] && j < i);  // top_k tie order
            rank[i] = r;
        }
        float d1 = 0.f, d2 = 0.f, d3 = 0.f;
        for (int i = 0; i < 32; i++) {
            float e = expf(v[i] - m);
            if (rank[i] < 16) d1 += e;   // C/2
            if (rank[i] < 21) d2 += e;   // 2C/3
            if (rank[i] < 24) d3 += e;   // 3C/4
        }
        float i1 = A1 / d1, i2 = A2 / d2, i3 = A3 / d3;
        for (int i = 0; i < 32; i++) {
            float e = expf(v[i] - m);
            float w = 0.f;
            if (rank[i] < 16) w += i1 * e;
            if (rank[i] < 21) w += i2 * e;
            if (rank[i] < 24) w += i3 * e;
            M[tid * 32 + i] = w;         // M[(head*32+c)*32 + d]
        }
    }
    __syncthreads();

    // Weff[cout][head*32+d] = sum_c wproj[cout][head*32+c] * M[head][c][d]
    for (int e = tid; e < 4096; e += 256) {
        int cout = e >> 6, j = e & 63;
        int head = j >> 5, dd = j & 31;
        const float* wp = wproj + cout * 64 + head * 32;
        const float* Mr = &M[head * 1024 + dd];
        float s = 0.f;
#pragma unroll
        for (int c = 0; c < 32; c++) s += __ldg(wp + c) * Mr[c * 32];
        g_weff[b * 4096 + e] = s;
    }
}

// ---------------- K4: out[b,o,n] = sum_j Weff[b,o,j] * v[b,j,n] -------------
__global__ void __launch_bounds__(256) k4_out(float* __restrict__ out) {
    int pb = blockIdx.x;
    int b  = blockIdx.y;
    __shared__ float ws[64 * 64];
    int tid = threadIdx.x;
    for (int i = tid; i < 4096; i += 256) ws[i] = g_weff[b * 4096 + i];
    __syncthreads();

    int ot = tid >> 6, qd = tid & 63;
    size_t p0 = (size_t)pb * 256 + qd * 4;
    const float* vb = g_v + (size_t)b * 64 * HW;

    float acc[16][4];
#pragma unroll
    for (int k = 0; k < 16; k++)
#pragma unroll
        for (int j = 0; j < 4; j++) acc[k][j] = 0.f;

    for (int j = 0; j < 64; j++) {
        float4 vv = *(const float4*)(vb + (size_t)j * HW + p0);
        const float* wr = &ws[(ot * 16) * 64 + j];
#pragma unroll
        for (int k = 0; k < 16; k++) {
            float w = wr[k * 64];
            acc[k][0] += w * vv.x; acc[k][1] += w * vv.y;
            acc[k][2] += w * vv.z; acc[k][3] += w * vv.w;
        }
    }
    float* ob = out + (size_t)b * 64 * HW;
#pragma unroll
    for (int k = 0; k < 16; k++) {
        float4 o = make_float4(acc[k][0], acc[k][1], acc[k][2], acc[k][3]);
        *(float4*)(ob + (size_t)(ot * 16 + k) * HW + p0) = o;
    }
}

// ---------------- launch -----------------------------------------------------
extern "C" void kernel_launch(void* const* d_in, const int* in_sizes, int n_in,
                              void* d_out, int out_size) {
    const float* x     = (const float*)d_in[0];
    const float* wqkv  = (const float*)d_in[1];
    const float* wdw   = (const float*)d_in[2];
    const float* wproj = (const float*)d_in[3];
    const float* temp  = (const float*)d_in[4];
    const float* a1    = (const float*)d_in[5];
    const float* a2    = (const float*)d_in[6];
    const float* a3    = (const float*)d_in[7];
    float* out = (float*)d_out;

    const int k2_smem = (336 + 2 * 32 * QK_PITCH) * (int)sizeof(float); // ~67 KB
    cudaFuncSetAttribute((const void*)k2_dw,
                         cudaFuncAttributeMaxDynamicSharedMemorySize, k2_smem);

    k0_zero<<<64, 256>>>();
    k1_conv1x1<<<dim3(3, 256, BATCH), 256>>>(x, wqkv);
    k2_dw<<<dim3(256, 4, BATCH), 256, k2_smem>>>(wdw);
    k3_attn<<<BATCH, 256>>>(wproj, temp, a1, a2, a3);
    k4_out<<<dim3(256, BATCH), 256>>>(out);
}

// round 2
// speedup vs baseline: 1.5859x; 1.5859x over previous
#include <cuda_runtime.h>
#include <cuda_bf16.h>
#include <math.h>

// Problem constants
#define BATCH 8
#define CIN   64
#define HEADS 2
#define CH    32          // channels per head
#define IMG   256
#define HW    65536       // IMG*IMG

typedef unsigned long long ull;

// ---------------- f32x2 packed-math helpers ---------------------------------
__device__ __forceinline__ ull pack2(float lo, float hi) {
    ull r;
    asm("mov.b64 %0, {%1, %2};" : "=l"(r) : "f"(lo), "f"(hi));
    return r;
}
__device__ __forceinline__ float2 unpack2(ull v) {
    float2 f;
    asm("mov.b64 {%0, %1}, %2;" : "=f"(f.x), "=f"(f.y) : "l"(v));
    return f;
}
__device__ __forceinline__ void ffma2(ull& d, ull a, ull b) {
    asm("fma.rn.f32x2 %0, %1, %2, %0;" : "+l"(d) : "l"(a), "l"(b));
}

// ---------------- scratch (static device globals; no allocation allowed) ----
__device__ float g_y1[(size_t)BATCH * 192 * HW];   // qkv after 1x1 conv
__device__ float g_v [(size_t)BATCH * 64  * HW];   // v after dwconv
__device__ float g_gram[BATCH * HEADS * CH * CH];  // q.k^T Gram per (b,head)
__device__ float g_sqq [BATCH * HEADS * CH];       // sum q^2 per channel
__device__ float g_sqk [BATCH * HEADS * CH];       // sum k^2 per channel
__device__ float g_weff[BATCH * 64 * 64];          // folded proj*attn matrix

// ---------------- K0: zero accumulators -------------------------------------
__global__ void k0_zero() {
    int i = blockIdx.x * 256 + threadIdx.x;
    if (i < BATCH * HEADS * CH * CH) g_gram[i] = 0.f;
    if (i < BATCH * HEADS * CH) { g_sqq[i] = 0.f; g_sqk[i] = 0.f; }
}

// ---------------- K1: 1x1 conv  y1[b,o,n] = sum_c wqkv[o,c]*x[b,c,n] --------
// grid (256 pixel-blocks, 8 batches); 3 out-channel groups looped inside so
// x re-reads hit L1/L2. f32x2: pairs of output channels per 64-bit FMA.
#define WPITCH 66
__global__ void __launch_bounds__(256) k1_conv1x1(const float* __restrict__ x,
                                                  const float* __restrict__ wqkv) {
    int pb = blockIdx.x;
    int b  = blockIdx.y;
    __shared__ float ws2[64 * WPITCH];   // [c][o_local] transposed, padded
    int tid = threadIdx.x;

    int ot = tid >> 6;                   // 0..3 -> outs [ot*16, ot*16+16)
    int qd = tid & 63;                   // 4 pixels each
    size_t p0 = (size_t)pb * 256 + qd * 4;
    const float* xb = x + (size_t)b * CIN * HW;

    for (int g = 0; g < 3; g++) {
        __syncthreads();
        for (int i = tid; i < 4096; i += 256) {
            int o = i >> 6, c = i & 63;
            ws2[c * WPITCH + o] = wqkv[g * 4096 + i];
        }
        __syncthreads();

        ull acc[8][4];
#pragma unroll
        for (int j = 0; j < 8; j++)
#pragma unroll
            for (int p = 0; p < 4; p++) acc[j][p] = 0ull;

        for (int c = 0; c < 64; c++) {
            float4 xv = *(const float4*)(xb + (size_t)c * HW + p0);
            ull xp0 = pack2(xv.x, xv.x), xp1 = pack2(xv.y, xv.y);
            ull xp2 = pack2(xv.z, xv.z), xp3 = pack2(xv.w, xv.w);
            const ull* wrow = (const ull*)&ws2[c * WPITCH + ot * 16];
#pragma unroll
            for (int j = 0; j < 8; j++) {
                ull wp = wrow[j];
                ffma2(acc[j][0], wp, xp0);
                ffma2(acc[j][1], wp, xp1);
                ffma2(acc[j][2], wp, xp2);
                ffma2(acc[j][3], wp, xp3);
            }
        }
        float* yb = g_y1 + ((size_t)b * 192 + g * 64) * HW;
#pragma unroll
        for (int j = 0; j < 8; j++) {
            float2 u0 = unpack2(acc[j][0]), u1 = unpack2(acc[j][1]);
            float2 u2 = unpack2(acc[j][2]), u3 = unpack2(acc[j][3]);
            int o = ot * 16 + 2 * j;
            *(float4*)(yb + (size_t)o * HW + p0)       = make_float4(u0.x, u1.x, u2.x, u3.x);
            *(float4*)(yb + (size_t)(o + 1) * HW + p0) = make_float4(u0.y, u1.y, u2.y, u3.y);
        }
    }
}

// ---------------- K2: depthwise 3x3 + Gram/sumsq (heads) or v write ---------
// grid (256 tiles of 16x16 px, 4 groups, 8 batches), 256 threads.
// 4 channels batched per halo phase (MLP), weights preloaded to smem,
// Gram in f32x2 over pixel pairs.
#define QK_PITCH 258
#define HALO_STRIDE 336
__global__ void __launch_bounds__(256) k2_dw(const float* __restrict__ wdw) {
    int t   = blockIdx.x;
    int grp = blockIdx.y;
    int b   = blockIdx.z;
    int py0 = (t >> 4) * 16, px0 = (t & 15) * 16;
    int tid = threadIdx.x;
    int ly = tid >> 4, lx = tid & 15;

    extern __shared__ float sm[];
    float* halo = sm;                           // 4 channels x 336
    float* wsm  = sm + 4 * HALO_STRIDE;         // up to 64*9 weights
    float* qt   = wsm + 64 * 9;                 // [32][QK_PITCH]
    float* kt   = qt + 32 * QK_PITCH;

    bool isHead = (grp < 2);
    int nch = isHead ? 64 : 32;

    // channel map + weight preload
    for (int i = tid; i < nch * 9; i += 256) {
        int c = i / 9, s = i - c * 9;
        int ych;
        if (isHead) ych = (c < 32) ? (grp * 32 + c) : (64 + grp * 32 + (c - 32));
        else        ych = 128 + (grp - 2) * 32 + c;
        wsm[i] = wdw[ych * 9 + s];
    }

    for (int cb = 0; cb < nch; cb += 4) {
        __syncthreads();
        // load 4 halos at once (MLP ~5 per thread)
        for (int i = tid; i < 4 * 324; i += 256) {
            int cc = i / 324;
            int r  = i - cc * 324;
            int hy = r / 18, hx = r - hy * 18;
            int gy = py0 - 1 + hy, gx = px0 - 1 + hx;
            int c = cb + cc;
            int ych;
            if (isHead) ych = (c < 32) ? (grp * 32 + c) : (64 + grp * 32 + (c - 32));
            else        ych = 128 + (grp - 2) * 32 + c;
            float v = 0.f;
            if (gy >= 0 && gy < IMG && gx >= 0 && gx < IMG)
                v = g_y1[((size_t)b * 192 + ych) * HW + gy * IMG + gx];
            halo[cc * HALO_STRIDE + hy * 18 + hx] = v;
        }
        __syncthreads();

#pragma unroll
        for (int cc = 0; cc < 4; cc++) {
            int c = cb + cc;
            const float* wd = &wsm[c * 9];
            const float* h0 = &halo[cc * HALO_STRIDE + (ly + 0) * 18 + lx];
            const float* h1 = &halo[cc * HALO_STRIDE + (ly + 1) * 18 + lx];
            const float* h2 = &halo[cc * HALO_STRIDE + (ly + 2) * 18 + lx];
            float acc = h0[0] * wd[0] + h0[1] * wd[1] + h0[2] * wd[2]
                      + h1[0] * wd[3] + h1[1] * wd[4] + h1[2] * wd[5]
                      + h2[0] * wd[6] + h2[1] * wd[7] + h2[2] * wd[8];
            if (isHead) {
                float* dst = (c < 32) ? &qt[c * QK_PITCH] : &kt[(c - 32) * QK_PITCH];
                dst[ly * 16 + lx] = acc;
            } else {
                int p = (py0 + ly) * IMG + (px0 + lx);
                g_v[((size_t)b * 64 + (grp - 2) * 32 + c) * HW + p] = acc;
            }
        }
    }

    if (!isHead) return;
    __syncthreads();

    // Gram: 2x2 (c,d) tile per thread, f32x2 over 128 pixel pairs.
    int c0 = (tid >> 4) * 2, d0 = (tid & 15) * 2;
    const ull* q0 = (const ull*)&qt[(c0 + 0) * QK_PITCH];
    const ull* q1 = (const ull*)&qt[(c0 + 1) * QK_PITCH];
    const ull* k0 = (const ull*)&kt[(d0 + 0) * QK_PITCH];
    const ull* k1 = (const ull*)&kt[(d0 + 1) * QK_PITCH];
    ull a00 = 0, a01 = 0, a10 = 0, a11 = 0;
#pragma unroll 4
    for (int pp = 0; pp < 128; pp++) {
        ull qv0 = q0[pp], qv1 = q1[pp], kv0 = k0[pp], kv1 = k1[pp];
        ffma2(a00, qv0, kv0); ffma2(a01, qv0, kv1);
        ffma2(a10, qv1, kv0); ffma2(a11, qv1, kv1);
    }
    float* gp = g_gram + ((b * HEADS + grp) * CH) * CH;
    float2 u;
    u = unpack2(a00); atomicAdd(&gp[(c0 + 0) * CH + d0 + 0], u.x + u.y);
    u = unpack2(a01); atomicAdd(&gp[(c0 + 0) * CH + d0 + 1], u.x + u.y);
    u = unpack2(a10); atomicAdd(&gp[(c0 + 1) * CH + d0 + 0], u.x + u.y);
    u = unpack2(a11); atomicAdd(&gp[(c0 + 1) * CH + d0 + 1], u.x + u.y);

    if (tid < 64) {
        int c = tid & 31;
        const ull* row = (tid < 32) ? (const ull*)&qt[c * QK_PITCH]
                                    : (const ull*)&kt[c * QK_PITCH];
        ull s = 0;
#pragma unroll 4
        for (int pp = 0; pp < 128; pp++) { ull v = row[pp]; ffma2(s, v, v); }
        float2 su = unpack2(s);
        float* dst = (tid < 32) ? &g_sqq[(b * HEADS + grp) * CH + c]
                                : &g_sqk[(b * HEADS + grp) * CH + c];
        atomicAdd(dst, su.x + su.y);
    }
}

// ---------------- K3: normalize Gram, triple top-k softmax, fold proj -------
__global__ void __launch_bounds__(256) k3_attn(const float* __restrict__ wproj,
                                               const float* __restrict__ temp,
                                               const float* __restrict__ a1p,
                                               const float* __restrict__ a2p,
                                               const float* __restrict__ a3p) {
    int b = blockIdx.x;
    int tid = threadIdx.x;
    __shared__ float attn[HEADS * CH * CH];
    __shared__ float M[HEADS * CH * CH];
    __shared__ float nq[HEADS * CH], nk[HEADS * CH];

    if (tid < 64) {
        nq[tid] = fmaxf(sqrtf(g_sqq[b * 64 + tid]), 1e-12f);
        nk[tid] = fmaxf(sqrtf(g_sqk[b * 64 + tid]), 1e-12f);
    }
    __syncthreads();
    for (int i = tid; i < 2048; i += 256) {
        int head = i >> 10, c = (i >> 5) & 31, d = i & 31;
        attn[i] = g_gram[b * 2048 + i] / (nq[head * 32 + c] * nk[head * 32 + d])
                * temp[head];
    }
    __syncthreads();

    float A1 = a1p[0], A2 = a2p[0], A3 = a3p[0];
    if (tid < 64) {                          // one row (head,c) per thread
        float v[32];
        const float* row = &attn[tid * 32];
#pragma unroll
        for (int i = 0; i < 32; i++) v[i] = row[i];
        float m = v[0];
#pragma unroll
        for (int i = 1; i < 32; i++) m = fmaxf(m, v[i]);

        int rank[32];
        for (int i = 0; i < 32; i++) {
            int r = 0;
            for (int j = 0; j < 32; j++)
                r += (v[j] > v[i]) || (v[j] == v[i] && j < i);  // top_k tie order
            rank[i] = r;
        }
        float d1 = 0.f, d2 = 0.f, d3 = 0.f;
        for (int i = 0; i < 32; i++) {
            float e = expf(v[i] - m);
            if (rank[i] < 16) d1 += e;   // C/2
            if (rank[i] < 21) d2 += e;   // 2C/3
            if (rank[i] < 24) d3 += e;   // 3C/4
        }
        float i1 = A1 / d1, i2 = A2 / d2, i3 = A3 / d3;
        for (int i = 0; i < 32; i++) {
            float e = expf(v[i] - m);
            float w = 0.f;
            if (rank[i] < 16) w += i1 * e;
            if (rank[i] < 21) w += i2 * e;
            if (rank[i] < 24) w += i3 * e;
            M[tid * 32 + i] = w;
        }
    }
    __syncthreads();

    // Weff[cout][head*32+d] = sum_c wproj[cout][head*32+c] * M[head][c][d]
    for (int e = tid; e < 4096; e += 256) {
        int cout = e >> 6, j = e & 63;
        int head = j >> 5, dd = j & 31;
        const float* wp = wproj + cout * 64 + head * 32;
        const float* Mr = &M[head * 1024 + dd];
        float s = 0.f;
#pragma unroll
        for (int c = 0; c < 32; c++) s += __ldg(wp + c) * Mr[c * 32];
        g_weff[b * 4096 + e] = s;
    }
}

// ---------------- K4: out[b,o,n] = sum_j Weff[b,o,j] * v[b,j,n] -------------
__global__ void __launch_bounds__(256) k4_out(float* __restrict__ out) {
    int pb = blockIdx.x;
    int b  = blockIdx.y;
    __shared__ float ws2[64 * WPITCH];   // [j][o] transposed, padded
    int tid = threadIdx.x;
    for (int i = tid; i < 4096; i += 256) {
        int o = i >> 6, j = i & 63;
        ws2[j * WPITCH + o] = g_weff[b * 4096 + i];
    }
    __syncthreads();

    int ot = tid >> 6, qd = tid & 63;
    size_t p0 = (size_t)pb * 256 + qd * 4;
    const float* vb = g_v + (size_t)b * 64 * HW;

    ull acc[8][4];
#pragma unroll
    for (int j = 0; j < 8; j++)
#pragma unroll
        for (int p = 0; p < 4; p++) acc[j][p] = 0ull;

    for (int j = 0; j < 64; j++) {
        float4 vv = *(const float4*)(vb + (size_t)j * HW + p0);
        ull xp0 = pack2(vv.x, vv.x), xp1 = pack2(vv.y, vv.y);
        ull xp2 = pack2(vv.z, vv.z), xp3 = pack2(vv.w, vv.w);
        const ull* wrow = (const ull*)&ws2[j * WPITCH + ot * 16];
#pragma unroll
        for (int k = 0; k < 8; k++) {
            ull wp = wrow[k];
            ffma2(acc[k][0], wp, xp0);
            ffma2(acc[k][1], wp, xp1);
            ffma2(acc[k][2], wp, xp2);
            ffma2(acc[k][3], wp, xp3);
        }
    }
    float* ob = out + (size_t)b * 64 * HW;
#pragma unroll
    for (int k = 0; k < 8; k++) {
        float2 u0 = unpack2(acc[k][0]), u1 = unpack2(acc[k][1]);
        float2 u2 = unpack2(acc[k][2]), u3 = unpack2(acc[k][3]);
        int o = ot * 16 + 2 * k;
        *(float4*)(ob + (size_t)o * HW + p0)       = make_float4(u0.x, u1.x, u2.x, u3.x);
        *(float4*)(ob + (size_t)(o + 1) * HW + p0) = make_float4(u0.y, u1.y, u2.y, u3.y);
    }
}

// ---------------- launch -----------------------------------------------------
extern "C" void kernel_launch(void* const* d_in, const int* in_sizes, int n_in,
                              void* d_out, int out_size) {
    const float* x     = (const float*)d_in[0];
    const float* wqkv  = (const float*)d_in[1];
    const float* wdw   = (const float*)d_in[2];
    const float* wproj = (const float*)d_in[3];
    const float* temp  = (const float*)d_in[4];
    const float* a1    = (const float*)d_in[5];
    const float* a2    = (const float*)d_in[6];
    const float* a3    = (const float*)d_in[7];
    float* out = (float*)d_out;

    const int k2_smem = (4 * HALO_STRIDE + 64 * 9 + 2 * 32 * QK_PITCH)
                        * (int)sizeof(float);   // ~72.5 KB
    cudaFuncSetAttribute((const void*)k2_dw,
                         cudaFuncAttributeMaxDynamicSharedMemorySize, k2_smem);

    k0_zero<<<64, 256>>>();
    k1_conv1x1<<<dim3(256, BATCH), 256>>>(x, wqkv);
    k2_dw<<<dim3(256, 4, BATCH), 256, k2_smem>>>(wdw);
    k3_attn<<<BATCH, 256>>>(wproj, temp, a1, a2, a3);
    k4_out<<<dim3(256, BATCH), 256>>>(out);
}

// round 5
// speedup vs baseline: 1.9076x; 1.2028x over previous
#include <cuda_runtime.h>
#include <cuda_bf16.h>
#include <math.h>

// Problem constants
#define BATCH 8
#define CIN   64
#define HEADS 2
#define CH    32
#define IMG   256
#define HW    65536

typedef unsigned long long ull;

// ---------------- f32x2 packed-math helpers ---------------------------------
__device__ __forceinline__ ull pack2(float lo, float hi) {
    ull r;
    asm("mov.b64 %0, {%1, %2};" : "=l"(r) : "f"(lo), "f"(hi));
    return r;
}
__device__ __forceinline__ float2 unpack2(ull v) {
    float2 f;
    asm("mov.b64 {%0, %1}, %2;" : "=f"(f.x), "=f"(f.y) : "l"(v));
    return f;
}
__device__ __forceinline__ void ffma2(ull& d, ull a, ull b) {
    asm("fma.rn.f32x2 %0, %1, %2, %0;" : "+l"(d) : "l"(a), "l"(b));
}

// ---------------- scratch ----------------------------------------------------
__device__ float g_v [(size_t)BATCH * 64 * HW];    // v after dwconv
__device__ float g_gram[BATCH * HEADS * CH * CH];
__device__ float g_sqq [BATCH * HEADS * CH];
__device__ float g_sqk [BATCH * HEADS * CH];
__device__ float g_weff[BATCH * 64 * 64];

// ---------------- K0: zero accumulators -------------------------------------
__global__ void k0_zero() {
    int i = blockIdx.x * 256 + threadIdx.x;
    if (i < BATCH * HEADS * CH * CH) g_gram[i] = 0.f;
    if (i < BATCH * HEADS * CH) { g_sqq[i] = 0.f; g_sqk[i] = 0.f; }
}

// ---------------- K12: fused 1x1 conv + dwconv3x3 + Gram / v write ----------
// One block per (16x16 tile, batch). Six 32-channel half-groups:
//   head0: q(ch 0..31)->qb, k(ch 64..95)->kb, Gram head0
//   head1: q(ch 32..63)->qb, k(ch 96..127)->kb, Gram head1
//   v: ch 128..159, 160..191 -> g_v
// smem layout (floats):
//   yh [32][324]  conv halo output          10368
//   qb [32][258]                             8256
//   kb [32][258]                             8256
//   wT [64][32]   1x1 weights (c-major)      2048   (dw 3x3 weights overlaid)
#define YH_PITCH 324
#define QK_PITCH 258
#define SM_YH 0
#define SM_QB (SM_YH + 32 * YH_PITCH)
#define SM_KB (SM_QB + 32 * QK_PITCH)
#define SM_WT (SM_KB + 32 * QK_PITCH)
#define SM_FLOATS (SM_WT + 64 * 32)

__global__ void __launch_bounds__(256, 2)
k12_fused(const float* __restrict__ x,
          const float* __restrict__ wqkv,
          const float* __restrict__ wdw) {
    int tile = blockIdx.x;
    int b    = blockIdx.y;
    int py0 = (tile >> 4) * 16, px0 = (tile & 15) * 16;
    int tid = threadIdx.x;

    extern __shared__ float sm[];
    float* yh = sm + SM_YH;
    float* qb = sm + SM_QB;
    float* kb = sm + SM_KB;
    float* wT = sm + SM_WT;
    ull*   wTu = (ull*)wT;

    // conv-phase mapping: slot = tid>>6 (4 ch-pairs), g = tid&63 (6 halo px)
    int slot = tid >> 6;
    int g    = tid & 63;

    // precompute halo pixel offsets + validity for this thread
    const float* xb = x + (size_t)b * CIN * HW;
    const float* xp[6];
    bool vld[6];
    int  pxi[6];
#pragma unroll
    for (int i = 0; i < 6; i++) {
        int p = (i < 5) ? (g + 64 * i) : (320 + g);
        bool v = (i < 5) || (g < 4);
        int hy = p / 18, hx = p - hy * 18;
        int gy = py0 - 1 + hy, gx = px0 - 1 + hx;
        v = v && (gy >= 0) && (gy < IMG) && (gx >= 0) && (gx < IMG);
        pxi[i] = p;
        vld[i] = v;
        xp[i] = xb + (v ? (gy * IMG + gx) : 0);
    }

    int ly = tid >> 4, lx = tid & 15;         // dwconv mapping: center pixel
    int cpix = (py0 + ly) * IMG + (px0 + lx); // gmem pixel for v writes

    // half-group schedule: chbase, destination (0=qb, 1=kb, 2=v)
    const int hg_base[6] = { 0, 64, 32, 96, 128, 160 };
    const int hg_dst [6] = { 0, 1,  0,  1,  2,   2   };

    for (int hg = 0; hg < 6; hg++) {
        int chbase = hg_base[hg];
        int dst    = hg_dst[hg];

        // ---- load 1x1 weights transposed: wT[c][o] = wqkv[(chbase+o)*64+c]
        __syncthreads();
#pragma unroll
        for (int r = 0; r < 8; r++) {
            int idx = tid + r * 256;          // 2048 entries
            int c = idx >> 5, o = idx & 31;
            wT[c * 32 + o] = wqkv[(chbase + o) * 64 + c];
        }
        __syncthreads();

        // ---- 1x1 conv into registers: 4 ch-pairs x 6 halo px
        ull acc[4][6];
#pragma unroll
        for (int j = 0; j < 4; j++)
#pragma unroll
            for (int i = 0; i < 6; i++) acc[j][i] = 0ull;

        for (int cb = 0; cb < 64; cb += 8) {
            const float* xq0 = xp[0] + (size_t)cb * HW;
            const float* xq1 = xp[1] + (size_t)cb * HW;
            const float* xq2 = xp[2] + (size_t)cb * HW;
            const float* xq3 = xp[3] + (size_t)cb * HW;
            const float* xq4 = xp[4] + (size_t)cb * HW;
            const float* xq5 = xp[5] + (size_t)cb * HW;
#pragma unroll
            for (int cc = 0; cc < 8; cc++) {
                int c = cb + cc;
                const ull* wr = wTu + c * 16 + slot * 4;
                ull w0 = wr[0], w1 = wr[1], w2 = wr[2], w3 = wr[3];

                float x0 = vld[0] ? xq0[(size_t)cc * HW] : 0.f;
                float x1 = vld[1] ? xq1[(size_t)cc * HW] : 0.f;
                float x2 = vld[2] ? xq2[(size_t)cc * HW] : 0.f;
                float x3 = vld[3] ? xq3[(size_t)cc * HW] : 0.f;
                float x4 = vld[4] ? xq4[(size_t)cc * HW] : 0.f;
                float x5 = vld[5] ? xq5[(size_t)cc * HW] : 0.f;
                ull xx0 = pack2(x0, x0), xx1 = pack2(x1, x1), xx2 = pack2(x2, x2);
                ull xx3 = pack2(x3, x3), xx4 = pack2(x4, x4), xx5 = pack2(x5, x5);

                ffma2(acc[0][0], w0, xx0); ffma2(acc[1][0], w1, xx0);
                ffma2(acc[2][0], w2, xx0); ffma2(acc[3][0], w3, xx0);
                ffma2(acc[0][1], w0, xx1); ffma2(acc[1][1], w1, xx1);
                ffma2(acc[2][1], w2, xx1); ffma2(acc[3][1], w3, xx1);
                ffma2(acc[0][2], w0, xx2); ffma2(acc[1][2], w1, xx2);
                ffma2(acc[2][2], w2, xx2); ffma2(acc[3][2], w3, xx2);
                ffma2(acc[0][3], w0, xx3); ffma2(acc[1][3], w1, xx3);
                ffma2(acc[2][3], w2, xx3); ffma2(acc[3][3], w3, xx3);
                ffma2(acc[0][4], w0, xx4); ffma2(acc[1][4], w1, xx4);
                ffma2(acc[2][4], w2, xx4); ffma2(acc[3][4], w3, xx4);
                ffma2(acc[0][5], w0, xx5); ffma2(acc[1][5], w1, xx5);
                ffma2(acc[2][5], w2, xx5); ffma2(acc[3][5], w3, xx5);
            }
        }

        // ---- spill conv halo to smem
#pragma unroll
        for (int j = 0; j < 4; j++) {
            int ch = 8 * slot + 2 * j;
#pragma unroll
            for (int i = 0; i < 6; i++) {
                if (i < 5 || g < 4) {
                    float2 u = unpack2(acc[j][i]);
                    yh[(ch + 0) * YH_PITCH + pxi[i]] = u.x;
                    yh[(ch + 1) * YH_PITCH + pxi[i]] = u.y;
                }
            }
        }
        __syncthreads();

        // ---- dw 3x3 weights into wT[0..287] (wT free until next hg)
        if (tid < 288) {
            int c = tid / 9, s = tid - c * 9;
            wT[tid] = wdw[(chbase + c) * 9 + s];
        }
        if (tid + 256 < 288) {
            int i2 = tid + 256;
            int c = i2 / 9, s = i2 - c * 9;
            wT[i2] = wdw[(chbase + c) * 9 + s];
        }
        __syncthreads();

        // ---- depthwise 3x3: thread = center pixel, loop 32 channels
        for (int c = 0; c < 32; c++) {
            const float* wd = &wT[c * 9];
            const float* h = &yh[c * YH_PITCH + ly * 18 + lx];
            float a = h[0]  * wd[0] + h[1]  * wd[1] + h[2]  * wd[2]
                    + h[18] * wd[3] + h[19] * wd[4] + h[20] * wd[5]
                    + h[36] * wd[6] + h[37] * wd[7] + h[38] * wd[8];
            if (dst == 0)      qb[c * QK_PITCH + tid] = a;
            else if (dst == 1) kb[c * QK_PITCH + tid] = a;
            else g_v[((size_t)b * 64 + (chbase - 128) + c) * HW + cpix] = a;
        }

        // ---- after k half-group: Gram + sum-of-squares for this head
        if (dst == 1) {
            int head = (hg == 1) ? 0 : 1;
            __syncthreads();
            int c0 = (tid >> 4) * 2, d0 = (tid & 15) * 2;
            const ull* q0 = (const ull*)&qb[(c0 + 0) * QK_PITCH];
            const ull* q1 = (const ull*)&qb[(c0 + 1) * QK_PITCH];
            const ull* k0 = (const ull*)&kb[(d0 + 0) * QK_PITCH];
            const ull* k1 = (const ull*)&kb[(d0 + 1) * QK_PITCH];
            ull a00 = 0, a01 = 0, a10 = 0, a11 = 0;
#pragma unroll 4
            for (int pp = 0; pp < 128; pp++) {
                ull qv0 = q0[pp], qv1 = q1[pp], kv0 = k0[pp], kv1 = k1[pp];
                ffma2(a00, qv0, kv0); ffma2(a01, qv0, kv1);
                ffma2(a10, qv1, kv0); ffma2(a11, qv1, kv1);
            }
            float* gp = g_gram + ((b * HEADS + head) * CH) * CH;
            float2 u;
            u = unpack2(a00); atomicAdd(&gp[(c0 + 0) * CH + d0 + 0], u.x + u.y);
            u = unpack2(a01); atomicAdd(&gp[(c0 + 0) * CH + d0 + 1], u.x + u.y);
            u = unpack2(a10); atomicAdd(&gp[(c0 + 1) * CH + d0 + 0], u.x + u.y);
            u = unpack2(a11); atomicAdd(&gp[(c0 + 1) * CH + d0 + 1], u.x + u.y);

            if (tid < 64) {
                int c = tid & 31;
                const ull* row = (tid < 32) ? (const ull*)&qb[c * QK_PITCH]
                                            : (const ull*)&kb[c * QK_PITCH];
                ull s = 0;
#pragma unroll 4
                for (int pp = 0; pp < 128; pp++) { ull v = row[pp]; ffma2(s, v, v); }
                float2 su = unpack2(s);
                float* dp = (tid < 32) ? &g_sqq[(b * HEADS + head) * CH + c]
                                       : &g_sqk[(b * HEADS + head) * CH + c];
                atomicAdd(dp, su.x + su.y);
            }
        }
    }
}

// ---------------- K3: normalize, triple top-k softmax (warp/row), fold proj -
__global__ void __launch_bounds__(256) k3_attn(const float* __restrict__ wproj,
                                               const float* __restrict__ temp,
                                               const float* __restrict__ a1p,
                                               const float* __restrict__ a2p,
                                               const float* __restrict__ a3p) {
    int b = blockIdx.x;
    int tid = threadIdx.x;
    int lane = tid & 31, wrp = tid >> 5;
    __shared__ float attn[HEADS * CH * CH];
    __shared__ float M[HEADS * CH * CH];
    __shared__ float nq[64], nk[64];

    if (tid < 64) {
        nq[tid] = fmaxf(sqrtf(g_sqq[b * 64 + tid]), 1e-12f);
        nk[tid] = fmaxf(sqrtf(g_sqk[b * 64 + tid]), 1e-12f);
    }
    __syncthreads();
    for (int i = tid; i < 2048; i += 256) {
        int head = i >> 10, c = (i >> 5) & 31, d = i & 31;
        attn[i] = g_gram[b * 2048 + i] / (nq[head * 32 + c] * nk[head * 32 + d])
                * temp[head];
    }
    __syncthreads();

    float A1 = a1p[0], A2 = a2p[0], A3 = a3p[0];
    for (int r = wrp; r < 64; r += 8) {        // warp per row
        float v = attn[r * 32 + lane];
        float m = v;
#pragma unroll
        for (int d = 16; d; d >>= 1) m = fmaxf(m, __shfl_xor_sync(~0u, m, d));
        int rk = 0;
#pragma unroll
        for (int j = 0; j < 32; j++) {
            float vj = __shfl_sync(~0u, v, j);
            rk += (vj > v) || (vj == v && j < lane);  // torch.topk tie order
        }
        float e = expf(v - m);
        float s1 = (rk < 16) ? e : 0.f;
        float s2 = (rk < 21) ? e : 0.f;
        float s3 = (rk < 24) ? e : 0.f;
#pragma unroll
        for (int d = 16; d; d >>= 1) {
            s1 += __shfl_xor_sync(~0u, s1, d);
            s2 += __shfl_xor_sync(~0u, s2, d);
            s3 += __shfl_xor_sync(~0u, s3, d);
        }
        float wgt = 0.f;
        if (rk < 16) wgt += A1 / s1 * e;
        if (rk < 21) wgt += A2 / s2 * e;
        if (rk < 24) wgt += A3 / s3 * e;
        M[r * 32 + lane] = wgt;
    }
    __syncthreads();

    // Weff[cout][head*32+d] = sum_c wproj[cout][head*32+c] * M[head][c][d]
    for (int e = tid; e < 4096; e += 256) {
        int cout = e >> 6, j = e & 63;
        int head = j >> 5, dd = j & 31;
        const float* wp = wproj + cout * 64 + head * 32;
        const float* Mr = &M[head * 1024 + dd];
        float s = 0.f;
#pragma unroll
        for (int c = 0; c < 32; c++) s += __ldg(wp + c) * Mr[c * 32];
        g_weff[b * 4096 + e] = s;
    }
}

// ---------------- K4: out[b,o,n] = sum_j Weff[b,o,j] * v[b,j,n] -------------
#define WPITCH 66
__global__ void __launch_bounds__(256) k4_out(float* __restrict__ out) {
    int pb = blockIdx.x;
    int b  = blockIdx.y;
    __shared__ float ws2[64 * WPITCH];
    int tid = threadIdx.x;
    for (int i = tid; i < 4096; i += 256) {
        int o = i >> 6, j = i & 63;
        ws2[j * WPITCH + o] = g_weff[b * 4096 + i];
    }
    __syncthreads();

    int ot = tid >> 6, qd = tid & 63;
    size_t p0 = (size_t)pb * 256 + qd * 4;
    const float* vb = g_v + (size_t)b * 64 * HW;

    ull acc[8][4];
#pragma unroll
    for (int j = 0; j < 8; j++)
#pragma unroll
        for (int p = 0; p < 4; p++) acc[j][p] = 0ull;

    for (int j = 0; j < 64; j++) {
        float4 vv = *(const float4*)(vb + (size_t)j * HW + p0);
        ull xp0 = pack2(vv.x, vv.x), xp1 = pack2(vv.y, vv.y);
        ull xp2 = pack2(vv.z, vv.z), xp3 = pack2(vv.w, vv.w);
        const ull* wrow = (const ull*)&ws2[j * WPITCH + ot * 16];
#pragma unroll
        for (int k = 0; k < 8; k++) {
            ull wp = wrow[k];
            ffma2(acc[k][0], wp, xp0);
            ffma2(acc[k][1], wp, xp1);
            ffma2(acc[k][2], wp, xp2);
            ffma2(acc[k][3], wp, xp3);
        }
    }
    float* ob = out + (size_t)b * 64 * HW;
#pragma unroll
    for (int k = 0; k < 8; k++) {
        float2 u0 = unpack2(acc[k][0]), u1 = unpack2(acc[k][1]);
        float2 u2 = unpack2(acc[k][2]), u3 = unpack2(acc[k][3]);
        int o = ot * 16 + 2 * k;
        *(float4*)(ob + (size_t)o * HW + p0)       = make_float4(u0.x, u1.x, u2.x, u3.x);
        *(float4*)(ob + (size_t)(o + 1) * HW + p0) = make_float4(u0.y, u1.y, u2.y, u3.y);
    }
}

// ---------------- launch -----------------------------------------------------
extern "C" void kernel_launch(void* const* d_in, const int* in_sizes, int n_in,
                              void* d_out, int out_size) {
    const float* x     = (const float*)d_in[0];
    const float* wqkv  = (const float*)d_in[1];
    const float* wdw   = (const float*)d_in[2];
    const float* wproj = (const float*)d_in[3];
    const float* temp  = (const float*)d_in[4];
    const float* a1    = (const float*)d_in[5];
    const float* a2    = (const float*)d_in[6];
    const float* a3    = (const float*)d_in[7];
    float* out = (float*)d_out;

    const int k12_smem = SM_FLOATS * (int)sizeof(float);   // ~113 KB
    cudaFuncSetAttribute((const void*)k12_fused,
                         cudaFuncAttributeMaxDynamicSharedMemorySize, k12_smem);

    k0_zero<<<64, 256>>>();
    k12_fused<<<dim3(256, BATCH), 256, k12_smem>>>(x, wqkv, wdw);
    k3_attn<<<BATCH, 256>>>(wproj, temp, a1, a2, a3);
    k4_out<<<dim3(256, BATCH), 256>>>(out);
}